// round 7
// baseline (speedup 1.0000x reference)
#include <cuda_runtime.h>
#include <cuda_pipeline.h>
#include <math.h>

// Problem shape (fixed by reference setup_inputs)
#define B   32
#define HW  12544
#define C   256
#define CR  16

#define NBLK  148            // one persistent CTA per SM — all resident (spin-safe)
#define MAXP  85             // blocks 0..111: 85 positions, 112..147: 84
#define MAXF4 (MAXP * 64)    // 5440 float4 per chunk max
#define KITER 21             // 21*256 = 5376 float4 (84-pos blocks exactly)

// Scratch (no cudaMalloc allowed); zero-initialized at module load
__device__ float        g_sums[B * C];
__device__ unsigned int g_cnt[B];
__device__ unsigned int g_cnt2[B];

__global__ __launch_bounds__(256, 1) void se_fused_kernel(
    const float* __restrict__ in,
    const float* __restrict__ w1, const float* __restrict__ b1,
    const float* __restrict__ w2, const float* __restrict__ b2,
    float* __restrict__ out)
{
    extern __shared__ float4 buf[];          // 2 * MAXF4 float4 (double buffer)
    __shared__ float4 s_red[256];
    __shared__ float  s_mean[C];
    __shared__ float  s_part[4][CR];
    __shared__ float  s_h[CR];
    __shared__ float  s_se[C];
    __shared__ int    s_last;

    const int blk  = blockIdx.x;
    const int tid  = threadIdx.x;
    const int qid  = tid & 63;               // channel quad (slots stride 256 ≡ 0 mod 64)
    const int prow = tid >> 6;

    const int  npos  = 84 + (blk < 112 ? 1 : 0);
    const int  start = blk * 84 + min(blk, 112);   // position offset within a batch
    const int  nf4   = npos * 64;                  // 5376 or 5440
    const bool xtra  = (nf4 > KITER * 256) && (tid < 64);

    const float4* in4  = reinterpret_cast<const float4*>(in);
    float4*       out4 = reinterpret_cast<float4*>(out);

    // ---------------- prime: load + sum + publish batch 0 ----------------
    {
        const float4* src = in4 + (size_t)start * 64;   // batch 0
        #pragma unroll
        for (int k = 0; k < KITER; k++)
            __pipeline_memcpy_async(&buf[tid + k * 256], &src[tid + k * 256], 16);
        if (xtra)
            __pipeline_memcpy_async(&buf[tid + KITER * 256], &src[tid + KITER * 256], 16);
        __pipeline_commit();
        __pipeline_wait_prior(0);
        __syncthreads();

        float4 a = make_float4(0.f, 0.f, 0.f, 0.f);
        #pragma unroll
        for (int k = 0; k < KITER; k++) {
            float4 v = buf[tid + k * 256];
            a.x += v.x; a.y += v.y; a.z += v.z; a.w += v.w;
        }
        if (xtra) {
            float4 v = buf[tid + KITER * 256];
            a.x += v.x; a.y += v.y; a.z += v.z; a.w += v.w;
        }
        s_red[tid] = a;
        __syncthreads();
        if (prow == 0) {
            float4 r0 = s_red[qid], r1 = s_red[qid + 64];
            float4 r2 = s_red[qid + 128], r3 = s_red[qid + 192];
            float* dst = &g_sums[4 * qid];
            atomicAdd(dst + 0, r0.x + r1.x + r2.x + r3.x);
            atomicAdd(dst + 1, r0.y + r1.y + r2.y + r3.y);
            atomicAdd(dst + 2, r0.z + r1.z + r2.z + r3.z);
            atomicAdd(dst + 3, r0.w + r1.w + r2.w + r3.w);
            __threadfence();
        }
        __syncthreads();
        if (tid == 0) { __threadfence(); atomicAdd(&g_cnt[0], 1u); }
    }

    // ---------------- main loop over batches ----------------
    for (int bb = 0; bb < B; bb++) {
        const int cur = bb & 1;
        float4* bcur = buf + cur * MAXF4;
        float4* bnxt = buf + (cur ^ 1) * MAXF4;

        // issue async load of batch bb+1 (flies during spin + MLP + scale)
        if (bb + 1 < B) {
            const float4* src = in4 + (size_t)(bb + 1) * (HW * 64) + (size_t)start * 64;
            #pragma unroll
            for (int k = 0; k < KITER; k++)
                __pipeline_memcpy_async(&bnxt[tid + k * 256], &src[tid + k * 256], 16);
            if (xtra)
                __pipeline_memcpy_async(&bnxt[tid + KITER * 256], &src[tid + KITER * 256], 16);
            __pipeline_commit();
        }

        // wait until all 148 blocks published sums for batch bb
        if (tid == 0) {
            volatile unsigned int* c = &g_cnt[bb];
            while (*c < NBLK) { }
            __threadfence();
        }
        __syncthreads();

        // ---- tiny MLP (redundant per block, inputs in L1/L2) ----
        s_mean[tid] = g_sums[bb * C + tid] * (1.0f / (float)HW);
        __syncthreads();
        if (tid < 64) {
            int j = tid & 15, part = tid >> 4, c0 = part * 64;
            float acc = 0.0f;
            #pragma unroll 8
            for (int c = c0; c < c0 + 64; c++)
                acc += s_mean[c] * w1[c * CR + j];
            s_part[part][j] = acc;
        }
        __syncthreads();
        if (tid < CR) {
            float acc = b1[tid] + s_part[0][tid] + s_part[1][tid]
                                + s_part[2][tid] + s_part[3][tid];
            s_h[tid] = fmaxf(acc, 0.0f);
        }
        __syncthreads();
        {
            float acc = b2[tid];
            #pragma unroll
            for (int j = 0; j < CR; j++)
                acc += s_h[j] * w2[j * C + tid];
            s_se[tid] = 1.0f / (1.0f + __expf(-acc));
        }

        // ---- reset protocol for batch bb (graph-replay safe) ----
        if (tid == 0) {
            unsigned int old = atomicAdd(&g_cnt2[bb], 1u);
            s_last = (old == NBLK - 1);
        }
        __syncthreads();   // also publishes s_se to the block
        if (s_last) {
            g_sums[bb * C + tid] = 0.0f;
            if (tid == 0) { g_cnt[bb] = 0u; g_cnt2[bb] = 0u; }
        }

        float4 sv = *reinterpret_cast<const float4*>(&s_se[4 * qid]);

        // ---- scale batch bb from smem, stream stores ----
        {
            float4* dst = out4 + (size_t)bb * (HW * 64) + (size_t)start * 64;
            #pragma unroll
            for (int k = 0; k < KITER; k++) {
                float4 v = bcur[tid + k * 256];
                v.x *= sv.x; v.y *= sv.y; v.z *= sv.z; v.w *= sv.w;
                __stcs(&dst[tid + k * 256], v);
            }
            if (xtra) {
                float4 v = bcur[tid + KITER * 256];
                v.x *= sv.x; v.y *= sv.y; v.z *= sv.z; v.w *= sv.w;
                __stcs(&dst[tid + KITER * 256], v);
            }
        }

        // ---- finish async load of bb+1, publish its sums ----
        if (bb + 1 < B) {
            __pipeline_wait_prior(0);
            __syncthreads();
            float4 a = make_float4(0.f, 0.f, 0.f, 0.f);
            #pragma unroll
            for (int k = 0; k < KITER; k++) {
                float4 v = bnxt[tid + k * 256];
                a.x += v.x; a.y += v.y; a.z += v.z; a.w += v.w;
            }
            if (xtra) {
                float4 v = bnxt[tid + KITER * 256];
                a.x += v.x; a.y += v.y; a.z += v.z; a.w += v.w;
            }
            s_red[tid] = a;
            __syncthreads();
            if (prow == 0) {
                float4 r0 = s_red[qid], r1 = s_red[qid + 64];
                float4 r2 = s_red[qid + 128], r3 = s_red[qid + 192];
                float* dst = &g_sums[(bb + 1) * C + 4 * qid];
                atomicAdd(dst + 0, r0.x + r1.x + r2.x + r3.x);
                atomicAdd(dst + 1, r0.y + r1.y + r2.y + r3.y);
                atomicAdd(dst + 2, r0.z + r1.z + r2.z + r3.z);
                atomicAdd(dst + 3, r0.w + r1.w + r2.w + r3.w);
                __threadfence();
            }
            __syncthreads();
            if (tid == 0) { __threadfence(); atomicAdd(&g_cnt[bb + 1], 1u); }
        }
    }
}

// ---------------------------------------------------------------------------
extern "C" void kernel_launch(void* const* d_in, const int* in_sizes, int n_in,
                              void* d_out, int out_size)
{
    const float* in = (const float*)d_in[0];
    const float* w1 = (const float*)d_in[1];
    const float* b1 = (const float*)d_in[2];
    const float* w2 = (const float*)d_in[3];
    const float* b2 = (const float*)d_in[4];
    float* out = (float*)d_out;

    const int smem = 2 * MAXF4 * (int)sizeof(float4);   // 174080 B
    cudaFuncSetAttribute(se_fused_kernel,
                         cudaFuncAttributeMaxDynamicSharedMemorySize, smem);
    se_fused_kernel<<<NBLK, 256, smem>>>(in, w1, b1, w2, b2, out);
}